// round 1
// baseline (speedup 1.0000x reference)
#include <cuda_runtime.h>

// Problem constants
#define B 1024
#define T 30
#define M 20
#define TWO_T (2*T)

// Output layout (concatenated fp32, reference tuple order)
#define N_PROBS_TRAJ   (B*M)                       // 20480
#define N_LOC          (B*M*TWO_T)                 // 1228800
#define N_CHOL_FULL    (B*M*TWO_T*TWO_T)           // 73728000
#define N_STEP_PROBS   (B*T*M)                     // 614400
#define N_MU           (B*T*M*2)                   // 1228800
#define N_CHOL_STEP    (B*T*M*4)                   // 2457600

#define O_PROBS_TRAJ   0
#define O_LOC          (O_PROBS_TRAJ + N_PROBS_TRAJ)   // 20480
#define O_CHOL_FULL    (O_LOC + N_LOC)                 // 1249280
#define O_STEP_PROBS   (O_CHOL_FULL + N_CHOL_FULL)     // 74977280
#define O_MU           (O_STEP_PROBS + N_STEP_PROBS)   // 75591680
#define O_CHOL_STEP    (O_MU + N_MU)                   // 76820480

#define VAR_EPS 1e-6f
#define PRUNE_DELTA 0.02f
#define PRUNE_TAU   0.1f
#define PRUNE_EPS   1e-8f

// ---------------------------------------------------------------------------
// Kernel 1: zero-fill the chol_full region (pure ST.128 stream, HBM-bound)
// ---------------------------------------------------------------------------
__global__ void fill_zero_f4(float4* __restrict__ p, int n4) {
    int i = blockIdx.x * blockDim.x + threadIdx.x;
    if (i < n4) p[i] = make_float4(0.f, 0.f, 0.f, 0.f);
}

// ---------------------------------------------------------------------------
// Kernel 2: per-(b,t,m) parameter expansion + scatter of Cholesky entries
// ---------------------------------------------------------------------------
__global__ void mdn_compute(const float* __restrict__ ml, float* __restrict__ out) {
    int i = blockIdx.x * blockDim.x + threadIdx.x;   // i = (b*T + t)*M + m
    if (i >= B * T * M) return;
    int m  = i % M;
    int bt = i / M;
    int t  = bt % T;
    int b  = bt / T;

    const float* p = ml + (size_t)i * 5;  // input layout matches i exactly
    float mu_x = p[0];
    float mu_y = p[1];
    float sx   = sqrtf(expf(p[2]) + VAR_EPS);
    float sy   = sqrtf(expf(p[3]) + VAR_EPS);
    float rho  = tanhf(p[4]);

    float L11 = sx;
    float L21 = rho * sy;
    float L22 = sy * sqrtf(fmaxf(1.0f - rho * rho, 0.0f));

    // loc [B, M, 2T]
    int loc_idx = O_LOC + (b * M + m) * TWO_T + 2 * t;
    out[loc_idx]     = mu_x;
    out[loc_idx + 1] = mu_y;

    // chol_full [B, M, 2T, 2T]: entries (2t,2t), (2t+1,2t), (2t+1,2t+1)
    int cb = O_CHOL_FULL + ((b * M + m) * TWO_T + 2 * t) * TWO_T + 2 * t;
    out[cb]             = L11;
    out[cb + TWO_T]     = L21;
    out[cb + TWO_T + 1] = L22;

    // mu [B, T, M, 2] (float2 aligned: O_MU even, i*2 even)
    *reinterpret_cast<float2*>(out + O_MU + i * 2) = make_float2(mu_x, mu_y);

    // chol_step [B, T, M, 2, 2] = [L11, 0, L21, L22] (float4 aligned)
    *reinterpret_cast<float4*>(out + O_CHOL_STEP + i * 4) =
        make_float4(L11, 0.0f, L21, L22);
}

// ---------------------------------------------------------------------------
// Kernel 3: pruned softmax over rows of M=20 (one thread per row, in regs)
//   p      = softmax(logits)
//   gate   = sigmoid((p - delta)/tau)
//   p_new  = p*gate / (sum(p*gate) + eps)
//   result = softmax(log(p_new + eps)) == (p_new + eps) / sum(p_new + eps)
// ---------------------------------------------------------------------------
__global__ void prune_softmax_rows(const float* __restrict__ in,
                                   float* __restrict__ out, int nrows) {
    int r = blockIdx.x * blockDim.x + threadIdx.x;
    if (r >= nrows) return;
    const float* x = in + (size_t)r * M;
    float v[M];

    float mx = -1e30f;
    #pragma unroll
    for (int j = 0; j < M; j++) { v[j] = x[j]; mx = fmaxf(mx, v[j]); }

    float s = 0.f;
    #pragma unroll
    for (int j = 0; j < M; j++) { v[j] = expf(v[j] - mx); s += v[j]; }
    float inv_s = 1.0f / s;

    float s2 = 0.f;
    #pragma unroll
    for (int j = 0; j < M; j++) {
        float pj   = v[j] * inv_s;
        float gate = 1.0f / (1.0f + expf(-(pj - PRUNE_DELTA) / PRUNE_TAU));
        float pt   = pj * gate;
        v[j] = pt;
        s2 += pt;
    }
    float inv_s2 = 1.0f / (s2 + PRUNE_EPS);

    float s3 = 0.f;
    #pragma unroll
    for (int j = 0; j < M; j++) {
        float pn = v[j] * inv_s2 + PRUNE_EPS;
        v[j] = pn;
        s3 += pn;
    }
    float inv_s3 = 1.0f / s3;

    float* o = out + (size_t)r * M;
    #pragma unroll
    for (int j = 0; j < M; j++) o[j] = v[j] * inv_s3;
}

// ---------------------------------------------------------------------------
extern "C" void kernel_launch(void* const* d_in, const int* in_sizes, int n_in,
                              void* d_out, int out_size) {
    const float* ml   = (const float*)d_in[0];   // mixture_latent [B, T, M*5]
    const float* trajw = (const float*)d_in[1];  // per_traj_weight [B, M]
    const float* stepw = (const float*)d_in[2];  // per_step_weight [B, T*M]
    float* out = (float*)d_out;

    // 1) zero chol_full region (dominant cost, ~295 MB of stores)
    int n4 = N_CHOL_FULL / 4;
    fill_zero_f4<<<(n4 + 255) / 256, 256>>>(
        reinterpret_cast<float4*>(out + O_CHOL_FULL), n4);

    // 2) parameter expansion + sparse Cholesky scatter (after fill, same stream)
    int n = B * T * M;
    mdn_compute<<<(n + 255) / 256, 256>>>(ml, out);

    // 3) pruned softmaxes
    prune_softmax_rows<<<(B + 127) / 128, 128>>>(trajw, out + O_PROBS_TRAJ, B);
    prune_softmax_rows<<<(B * T + 127) / 128, 128>>>(stepw, out + O_STEP_PROBS, B * T);
}

// round 2
// speedup vs baseline: 1.6848x; 1.6848x over previous
#include <cuda_runtime.h>

// Problem constants
#define B 1024
#define T 30
#define M 20
#define TWO_T (2*T)
#define BLOCK_ELEMS (TWO_T*TWO_T)   // 3600 floats per (b,m) chol block
#define BLOCK_F4    (BLOCK_ELEMS/4) // 900 float4

// Output layout (concatenated fp32, reference tuple order)
#define N_PROBS_TRAJ   (B*M)
#define N_LOC          (B*M*TWO_T)
#define N_CHOL_FULL    (B*M*TWO_T*TWO_T)
#define N_STEP_PROBS   (B*T*M)
#define N_MU           (B*T*M*2)
#define N_CHOL_STEP    (B*T*M*4)

#define O_PROBS_TRAJ   0
#define O_LOC          (O_PROBS_TRAJ + N_PROBS_TRAJ)   // 20480
#define O_CHOL_FULL    (O_LOC + N_LOC)                 // 1249280
#define O_STEP_PROBS   (O_CHOL_FULL + N_CHOL_FULL)     // 74977280
#define O_MU           (O_STEP_PROBS + N_STEP_PROBS)   // 75591680
#define O_CHOL_STEP    (O_MU + N_MU)                   // 76820480

#define VAR_EPS 1e-6f
#define PRUNE_DELTA 0.02f
#define PRUNE_TAU   0.1f
#define PRUNE_EPS   1e-8f

#define TILES_TOTAL   (B*M)          // 20480
#define TILES_PER_CTA 8
#define CHOL_GRID     (TILES_TOTAL / TILES_PER_CTA)  // 2560

// ---------------------------------------------------------------------------
// Kernel A: chol_full (each 128B line written exactly once) + loc.
// One CTA iterates over TILES_PER_CTA (b,m) tiles. SMEM holds the 60x60
// template: zeroed once at CTA start; per tile only the 90 nonzeros are
// scattered and later re-zeroed by the same threads (no races).
// ---------------------------------------------------------------------------
__global__ void __launch_bounds__(256) chol_loc_kernel(
    const float* __restrict__ ml, float* __restrict__ out) {
    __shared__ float tile[BLOCK_ELEMS];

    // zero the template once
    #pragma unroll
    for (int q = threadIdx.x; q < BLOCK_F4; q += 256)
        *reinterpret_cast<float4*>(tile + 4 * q) = make_float4(0.f, 0.f, 0.f, 0.f);

    int tile0 = blockIdx.x * TILES_PER_CTA;
    for (int k = 0; k < TILES_PER_CTA; k++) {
        int tl = tile0 + k;        // tl = b*M + m
        int m = tl % M;
        int b = tl / M;

        // threads 0..29 compute params for their t and scatter into smem
        int t = threadIdx.x;
        if (t < T) {
            const float* p = ml + ((size_t)(b * T + t) * M + m) * 5;
            float mu_x = p[0];
            float mu_y = p[1];
            float sx   = sqrtf(expf(p[2]) + VAR_EPS);
            float sy   = sqrtf(expf(p[3]) + VAR_EPS);
            float rho  = tanhf(p[4]);

            float L11 = sx;
            float L21 = rho * sy;
            float L22 = sy * sqrtf(fmaxf(1.0f - rho * rho, 0.0f));

            int base = 122 * t;            // (2t)*60 + 2t
            tile[base]      = L11;
            tile[base + 60] = L21;         // (2t+1)*60 + 2t
            tile[base + 61] = L22;

            // loc [B,M,2T]
            float* lo = out + O_LOC + (size_t)tl * TWO_T + 2 * t;
            lo[0] = mu_x;
            lo[1] = mu_y;
        }
        __syncthreads();

        // stream the full 14.4KB block to gmem, coalesced float4
        float4* dst = reinterpret_cast<float4*>(out + O_CHOL_FULL + (size_t)tl * BLOCK_ELEMS);
        const float4* src = reinterpret_cast<const float4*>(tile);
        #pragma unroll
        for (int q = threadIdx.x; q < BLOCK_F4; q += 256)
            dst[q] = src[q];
        __syncthreads();

        // re-zero only the 90 touched positions (same threads wrote them)
        if (t < T) {
            int base = 122 * t;
            tile[base]      = 0.f;
            tile[base + 60] = 0.f;
            tile[base + 61] = 0.f;
        }
        // next iteration's first __syncthreads() orders these zeros
        // before the next copy loop's reads
    }
}

// ---------------------------------------------------------------------------
// Kernel B: dense outputs mu [B,T,M,2] and chol_step [B,T,M,2,2]
// ---------------------------------------------------------------------------
__global__ void mu_cholstep_kernel(const float* __restrict__ ml,
                                   float* __restrict__ out) {
    int i = blockIdx.x * blockDim.x + threadIdx.x;   // i = (b*T + t)*M + m
    if (i >= B * T * M) return;

    const float* p = ml + (size_t)i * 5;
    float mu_x = p[0];
    float mu_y = p[1];
    float sx   = sqrtf(expf(p[2]) + VAR_EPS);
    float sy   = sqrtf(expf(p[3]) + VAR_EPS);
    float rho  = tanhf(p[4]);

    float L11 = sx;
    float L21 = rho * sy;
    float L22 = sy * sqrtf(fmaxf(1.0f - rho * rho, 0.0f));

    *reinterpret_cast<float2*>(out + O_MU + (size_t)i * 2) = make_float2(mu_x, mu_y);
    *reinterpret_cast<float4*>(out + O_CHOL_STEP + (size_t)i * 4) =
        make_float4(L11, 0.0f, L21, L22);
}

// ---------------------------------------------------------------------------
// Kernel C: pruned softmax over rows of M=20, vectorized float4 I/O
//   softmax(log(p_new + eps)) == (p_new + eps)/sum(p_new + eps)
// ---------------------------------------------------------------------------
__global__ void prune_softmax_rows(const float* __restrict__ in,
                                   float* __restrict__ out, int nrows) {
    int r = blockIdx.x * blockDim.x + threadIdx.x;
    if (r >= nrows) return;
    const float4* x4 = reinterpret_cast<const float4*>(in + (size_t)r * M);
    float v[M];
    #pragma unroll
    for (int q = 0; q < M / 4; q++) {
        float4 f = x4[q];
        v[4*q] = f.x; v[4*q+1] = f.y; v[4*q+2] = f.z; v[4*q+3] = f.w;
    }

    float mx = v[0];
    #pragma unroll
    for (int j = 1; j < M; j++) mx = fmaxf(mx, v[j]);

    float s = 0.f;
    #pragma unroll
    for (int j = 0; j < M; j++) { v[j] = expf(v[j] - mx); s += v[j]; }
    float inv_s = 1.0f / s;

    float s2 = 0.f;
    #pragma unroll
    for (int j = 0; j < M; j++) {
        float pj   = v[j] * inv_s;
        float gate = 1.0f / (1.0f + expf(-(pj - PRUNE_DELTA) / PRUNE_TAU));
        float pt   = pj * gate;
        v[j] = pt;
        s2 += pt;
    }
    float inv_s2 = 1.0f / (s2 + PRUNE_EPS);

    float s3 = 0.f;
    #pragma unroll
    for (int j = 0; j < M; j++) {
        float pn = v[j] * inv_s2 + PRUNE_EPS;
        v[j] = pn;
        s3 += pn;
    }
    float inv_s3 = 1.0f / s3;

    float4* o4 = reinterpret_cast<float4*>(out + (size_t)r * M);
    #pragma unroll
    for (int q = 0; q < M / 4; q++)
        o4[q] = make_float4(v[4*q] * inv_s3, v[4*q+1] * inv_s3,
                            v[4*q+2] * inv_s3, v[4*q+3] * inv_s3);
}

// ---------------------------------------------------------------------------
extern "C" void kernel_launch(void* const* d_in, const int* in_sizes, int n_in,
                              void* d_out, int out_size) {
    const float* ml    = (const float*)d_in[0];  // mixture_latent [B, T, M*5]
    const float* trajw = (const float*)d_in[1];  // per_traj_weight [B, M]
    const float* stepw = (const float*)d_in[2];  // per_step_weight [B, T*M]
    float* out = (float*)d_out;

    chol_loc_kernel<<<CHOL_GRID, 256>>>(ml, out);

    int n = B * T * M;
    mu_cholstep_kernel<<<(n + 255) / 256, 256>>>(ml, out);

    prune_softmax_rows<<<(B + 127) / 128, 128>>>(trajw, out + O_PROBS_TRAJ, B);
    prune_softmax_rows<<<(B * T + 127) / 128, 128>>>(stepw, out + O_STEP_PROBS, B * T);
}

// round 4
// speedup vs baseline: 2.1395x; 1.2698x over previous
#include <cuda_runtime.h>

// Problem constants
#define B 1024
#define T 30
#define M 20
#define TWO_T (2*T)
#define BLOCK_ELEMS (TWO_T*TWO_T)   // 3600 floats per (b,m) chol block
#define BLOCK_F4    (BLOCK_ELEMS/4) // 900 float4

// Output layout (concatenated fp32, reference tuple order)
#define N_PROBS_TRAJ   (B*M)
#define N_LOC          (B*M*TWO_T)
#define N_CHOL_FULL    (B*M*TWO_T*TWO_T)
#define N_STEP_PROBS   (B*T*M)
#define N_MU           (B*T*M*2)
#define N_CHOL_STEP    (B*T*M*4)

#define O_PROBS_TRAJ   0
#define O_LOC          (O_PROBS_TRAJ + N_PROBS_TRAJ)   // 20480
#define O_CHOL_FULL    (O_LOC + N_LOC)                 // 1249280
#define O_STEP_PROBS   (O_CHOL_FULL + N_CHOL_FULL)     // 74977280
#define O_MU           (O_STEP_PROBS + N_STEP_PROBS)   // 75591680
#define O_CHOL_STEP    (O_MU + N_MU)                   // 76820480

#define VAR_EPS 1e-6f
#define PRUNE_DELTA 0.02f
#define PRUNE_TAU   0.1f
#define PRUNE_EPS   1e-8f

#define TILES_TOTAL   (B*M)                         // 20480
#define TILES_PER_CTA 8
#define CHOL_CTAS     (TILES_TOTAL / TILES_PER_CTA) // 2560

#define SM_ROWS       (B + B*T)                     // 31744 softmax rows total
#define SM_CTAS       (SM_ROWS / 256)               // 124 (exact)
#define GRID_TOTAL    (SM_CTAS + CHOL_CTAS)         // 2684

// ---------------------------------------------------------------------------
// Fused kernel.
//   blocks [0, SM_CTAS): pruned softmax rows (traj + step, unified)
//   blocks [SM_CTAS, GRID_TOTAL): 8 chol tiles each + dense outputs
// ---------------------------------------------------------------------------
__global__ void __launch_bounds__(256) mdn_fused(
    const float* __restrict__ ml,     // [B, T, M*5]
    const float* __restrict__ trajw,  // [B, M]
    const float* __restrict__ stepw,  // [B, T*M]
    float* __restrict__ out) {

    // float4 per (tile, t): {L11, L21, L22, 0}
    __shared__ float4 Ls[TILES_PER_CTA][T];

    int bid = blockIdx.x;
    int tid = threadIdx.x;

    if (bid < SM_CTAS) {
        // ---------------- pruned softmax path ----------------
        // softmax(log(p_new + eps)) == (p_new + eps)/sum(p_new + eps)
        int r = bid * 256 + tid;          // [0, 31744)
        const float* x;
        float* o;
        if (r < B) {
            x = trajw + (size_t)r * M;
            o = out + O_PROBS_TRAJ + (size_t)r * M;
        } else {
            int rr = r - B;
            x = stepw + (size_t)rr * M;
            o = out + O_STEP_PROBS + (size_t)rr * M;
        }
        float v[M];
        const float4* x4 = reinterpret_cast<const float4*>(x);
        #pragma unroll
        for (int q = 0; q < M / 4; q++) {
            float4 f = x4[q];
            v[4*q] = f.x; v[4*q+1] = f.y; v[4*q+2] = f.z; v[4*q+3] = f.w;
        }
        float mx = v[0];
        #pragma unroll
        for (int j = 1; j < M; j++) mx = fmaxf(mx, v[j]);
        float s = 0.f;
        #pragma unroll
        for (int j = 0; j < M; j++) { v[j] = __expf(v[j] - mx); s += v[j]; }
        float inv_s = 1.0f / s;
        float s2 = 0.f;
        #pragma unroll
        for (int j = 0; j < M; j++) {
            float pj   = v[j] * inv_s;
            float gate = 1.0f / (1.0f + __expf(-(pj - PRUNE_DELTA) / PRUNE_TAU));
            float pt   = pj * gate;
            v[j] = pt;
            s2 += pt;
        }
        float inv_s2 = 1.0f / (s2 + PRUNE_EPS);
        float s3 = 0.f;
        #pragma unroll
        for (int j = 0; j < M; j++) {
            float pn = v[j] * inv_s2 + PRUNE_EPS;
            v[j] = pn;
            s3 += pn;
        }
        float inv_s3 = 1.0f / s3;
        float4* o4 = reinterpret_cast<float4*>(o);
        #pragma unroll
        for (int q = 0; q < M / 4; q++)
            o4[q] = make_float4(v[4*q] * inv_s3, v[4*q+1] * inv_s3,
                                v[4*q+2] * inv_s3, v[4*q+3] * inv_s3);
        return;
    }

    // ---------------- chol + dense path ----------------
    int tile0 = (bid - SM_CTAS) * TILES_PER_CTA;

    // Phase 1: threads 0..239 -> (t = tid/8, k = tid%8); compute params,
    // write mu / chol_step / loc, stash Ls in smem.
    if (tid < TILES_PER_CTA * T) {
        int k = tid & 7;
        int t = tid >> 3;
        int tl = tile0 + k;            // tl = b*M + m
        int m = tl % M;
        int b = tl / M;
        int i = (b * T + t) * M + m;   // dense index (b,t,m)

        const float* p = ml + (size_t)i * 5;
        float mu_x = p[0];
        float mu_y = p[1];
        float sx   = sqrtf(expf(p[2]) + VAR_EPS);
        float sy   = sqrtf(expf(p[3]) + VAR_EPS);
        float rho  = tanhf(p[4]);

        float L11 = sx;
        float L21 = rho * sy;
        float L22 = sy * sqrtf(fmaxf(1.0f - rho * rho, 0.0f));

        Ls[k][t] = make_float4(L11, L21, L22, 0.f);

        // mu [B,T,M,2]
        *reinterpret_cast<float2*>(out + O_MU + (size_t)i * 2) =
            make_float2(mu_x, mu_y);
        // chol_step [B,T,M,2,2] = [L11, 0, L21, L22]
        *reinterpret_cast<float4*>(out + O_CHOL_STEP + (size_t)i * 4) =
            make_float4(L11, 0.0f, L21, L22);
        // loc [B,M,2T]
        *reinterpret_cast<float2*>(out + O_LOC + (size_t)tl * TWO_T + 2 * t) =
            make_float2(mu_x, mu_y);
    }
    __syncthreads();

    // Phase 2: stream all 8 tiles. Thread owns f4 slots q = tid + 256*s.
    // Slot geometry is tile-invariant; precompute once.
    int   s_t[4];       // t for this slot
    bool  s_diag[4];    // slot contains diagonal entries
    bool  s_odd[4];     // odd row (L21/L22) vs even row (L11)
    bool  s_hi[4];      // values in .z/.w vs .x/.y
    bool  s_on[4];      // slot in range
    #pragma unroll
    for (int s = 0; s < 4; s++) {
        int q = tid + 256 * s;
        s_on[s] = (q < BLOCK_F4);
        int r  = q / 15;
        int c4 = q % 15;
        int t  = r >> 1;
        if (t > T - 1) t = T - 1;      // clamp for out-of-range slots
        s_t[s]    = t;
        s_diag[s] = (c4 == (t >> 1));
        s_odd[s]  = (r & 1);
        s_hi[s]   = (t & 1);
    }

    float4* dst = reinterpret_cast<float4*>(out + O_CHOL_FULL) +
                  (size_t)tile0 * BLOCK_F4 + tid;
    const float4 z4 = make_float4(0.f, 0.f, 0.f, 0.f);

    #pragma unroll
    for (int k = 0; k < TILES_PER_CTA; k++) {
        #pragma unroll
        for (int s = 0; s < 4; s++) {
            if (s_on[s]) {
                float4 v = z4;
                if (s_diag[s]) {
                    float4 L = Ls[k][s_t[s]];
                    float lo = s_odd[s] ? L.y : L.x;   // L21 : L11
                    float hi = s_odd[s] ? L.z : 0.f;   // L22 : 0
                    if (s_hi[s]) { v.z = lo; v.w = hi; }
                    else         { v.x = lo; v.y = hi; }
                }
                dst[256 * s] = v;
            }
        }
        dst += BLOCK_F4;
    }
}

// ---------------------------------------------------------------------------
extern "C" void kernel_launch(void* const* d_in, const int* in_sizes, int n_in,
                              void* d_out, int out_size) {
    const float* ml    = (const float*)d_in[0];  // mixture_latent
    const float* trajw = (const float*)d_in[1];  // per_traj_weight
    const float* stepw = (const float*)d_in[2];  // per_step_weight
    float* out = (float*)d_out;

    mdn_fused<<<GRID_TOTAL, 256>>>(ml, trajw, stepw, out);
}

// round 8
// speedup vs baseline: 2.4024x; 1.1229x over previous
#include <cuda_runtime.h>

// Problem constants
#define B 1024
#define T 30
#define M 20
#define TWO_T (2*T)
#define BLOCK_ELEMS (TWO_T*TWO_T)   // 3600 floats per (b,m) chol block
#define BLOCK_F4    (BLOCK_ELEMS/4) // 900 float4

// Output layout (concatenated fp32, reference tuple order)
#define N_PROBS_TRAJ   (B*M)
#define N_LOC          (B*M*TWO_T)
#define N_CHOL_FULL    (B*M*TWO_T*TWO_T)
#define N_STEP_PROBS   (B*T*M)
#define N_MU           (B*T*M*2)
#define N_CHOL_STEP    (B*T*M*4)

#define O_PROBS_TRAJ   0
#define O_LOC          (O_PROBS_TRAJ + N_PROBS_TRAJ)   // 20480
#define O_CHOL_FULL    (O_LOC + N_LOC)                 // 1249280
#define O_STEP_PROBS   (O_CHOL_FULL + N_CHOL_FULL)     // 74977280
#define O_MU           (O_STEP_PROBS + N_STEP_PROBS)   // 75591680
#define O_CHOL_STEP    (O_MU + N_MU)                   // 76820480

#define VAR_EPS 1e-6f
#define PRUNE_DELTA 0.02f
#define PRUNE_TAU   0.1f
#define PRUNE_EPS   1e-8f

#define TILES_TOTAL   (B*M)                         // 20480
#define TILES_PER_CTA 8
#define CHOL_CTAS     (TILES_TOTAL / TILES_PER_CTA) // 2560

#define SM_ROWS       (B + B*T)                     // 31744 softmax rows total
#define SM_CTAS       (SM_ROWS / 256)               // 124 (exact)
#define GRID_TOTAL    (SM_CTAS + CHOL_CTAS)         // 2684

// smem: per tile k, 61 float4 rows: rows 0..59 = diag f4 for that row,
// row 60 = zero f4 (shared source for all non-diag slots)
#define ROWS_PER_TILE 61

// ---------------------------------------------------------------------------
__global__ void __launch_bounds__(256) mdn_fused(
    const float* __restrict__ ml,     // [B, T, M*5]
    const float* __restrict__ trajw,  // [B, M]
    const float* __restrict__ stepw,  // [B, T*M]
    float* __restrict__ out) {

    __shared__ float4 DiagVal[TILES_PER_CTA * ROWS_PER_TILE];

    int bid = blockIdx.x;
    int tid = threadIdx.x;

    if (bid < SM_CTAS) {
        // ---------------- pruned softmax path ----------------
        // softmax(log(p_new + eps)) == (p_new + eps)/sum(p_new + eps)
        int r = bid * 256 + tid;          // [0, 31744)
        const float* x;
        float* o;
        if (r < B) {
            x = trajw + (size_t)r * M;
            o = out + O_PROBS_TRAJ + (size_t)r * M;
        } else {
            int rr = r - B;
            x = stepw + (size_t)rr * M;
            o = out + O_STEP_PROBS + (size_t)rr * M;
        }
        float v[M];
        const float4* x4 = reinterpret_cast<const float4*>(x);
        #pragma unroll
        for (int q = 0; q < M / 4; q++) {
            float4 f = x4[q];
            v[4*q] = f.x; v[4*q+1] = f.y; v[4*q+2] = f.z; v[4*q+3] = f.w;
        }
        float mx = v[0];
        #pragma unroll
        for (int j = 1; j < M; j++) mx = fmaxf(mx, v[j]);
        float s = 0.f;
        #pragma unroll
        for (int j = 0; j < M; j++) { v[j] = __expf(v[j] - mx); s += v[j]; }
        float inv_s = 1.0f / s;
        float s2 = 0.f;
        #pragma unroll
        for (int j = 0; j < M; j++) {
            float pj   = v[j] * inv_s;
            float gate = 1.0f / (1.0f + __expf(-(pj - PRUNE_DELTA) / PRUNE_TAU));
            float pt   = pj * gate;
            v[j] = pt;
            s2 += pt;
        }
        float inv_s2 = 1.0f / (s2 + PRUNE_EPS);
        float s3 = 0.f;
        #pragma unroll
        for (int j = 0; j < M; j++) {
            float pn = v[j] * inv_s2 + PRUNE_EPS;
            v[j] = pn;
            s3 += pn;
        }
        float inv_s3 = 1.0f / s3;
        float4* o4 = reinterpret_cast<float4*>(o);
        #pragma unroll
        for (int q = 0; q < M / 4; q++)
            o4[q] = make_float4(v[4*q] * inv_s3, v[4*q+1] * inv_s3,
                                v[4*q+2] * inv_s3, v[4*q+3] * inv_s3);
        return;
    }

    // ---------------- chol + dense path ----------------
    int tile0 = (bid - SM_CTAS) * TILES_PER_CTA;

    // Phase 1: threads 0..239 -> (t = tid>>3, k = tid&7); compute params,
    // write mu / chol_step / loc, and bake the diag float4s into smem.
    if (tid < TILES_PER_CTA * T) {
        int k = tid & 7;
        int t = tid >> 3;
        int tl = tile0 + k;            // tl = b*M + m
        int m = tl % M;
        int b = tl / M;
        int i = (b * T + t) * M + m;   // dense index (b,t,m)

        const float* p = ml + (size_t)i * 5;
        float mu_x = p[0];
        float mu_y = p[1];
        float sx   = sqrtf(expf(p[2]) + VAR_EPS);
        float sy   = sqrtf(expf(p[3]) + VAR_EPS);
        float rho  = tanhf(p[4]);

        float L11 = sx;
        float L21 = rho * sy;
        float L22 = sy * sqrtf(fmaxf(1.0f - rho * rho, 0.0f));

        // lane placement: diag col 2t occupies f4 lanes (2t&3, (2t&3)+1)
        bool hi = (t & 1);             // t odd -> values in .z/.w
        float4 ev = hi ? make_float4(0.f, 0.f, L11, 0.f)
                       : make_float4(L11, 0.f, 0.f, 0.f);
        float4 od = hi ? make_float4(0.f, 0.f, L21, L22)
                       : make_float4(L21, L22, 0.f, 0.f);
        DiagVal[k * ROWS_PER_TILE + 2 * t]     = ev;
        DiagVal[k * ROWS_PER_TILE + 2 * t + 1] = od;
        if (t == 0)
            DiagVal[k * ROWS_PER_TILE + 60] = make_float4(0.f, 0.f, 0.f, 0.f);

        // mu [B,T,M,2]
        *reinterpret_cast<float2*>(out + O_MU + (size_t)i * 2) =
            make_float2(mu_x, mu_y);
        // chol_step [B,T,M,2,2] = [L11, 0, L21, L22]
        *reinterpret_cast<float4*>(out + O_CHOL_STEP + (size_t)i * 4) =
            make_float4(L11, 0.0f, L21, L22);
        // loc [B,M,2T]
        *reinterpret_cast<float2*>(out + O_LOC + (size_t)tl * TWO_T + 2 * t) =
            make_float2(mu_x, mu_y);
    }
    __syncthreads();

    // Phase 2: each thread owns f4 slots q = tid + 256*s, s in [0,4).
    // Precompute per-slot smem row index: diag slots -> their row,
    // non-diag -> the zero row (60). Then the sweep is pure LDS.128 + STG.128.
    int  s_idx[4];      // smem row index within a tile block
    bool s_on[4];
    #pragma unroll
    for (int s = 0; s < 4; s++) {
        int q = tid + 256 * s;
        s_on[s] = (q < BLOCK_F4);
        int r  = q / 15;
        int c4 = q % 15;
        int t  = r >> 1;
        bool diag = s_on[s] && (c4 == (t >> 1)) && (t < T);
        s_idx[s] = diag ? r : 60;
    }

    float4* dst = reinterpret_cast<float4*>(out + O_CHOL_FULL) +
                  (size_t)tile0 * BLOCK_F4 + tid;
    const float4* diag_base = DiagVal;

    #pragma unroll
    for (int k = 0; k < TILES_PER_CTA; k++) {
        #pragma unroll
        for (int s = 0; s < 4; s++) {
            if (s_on[s]) {
                float4 v = diag_base[s_idx[s]];
                __stcs(dst + 256 * s, v);
            }
        }
        diag_base += ROWS_PER_TILE;
        dst += BLOCK_F4;
    }
}

// ---------------------------------------------------------------------------
extern "C" void kernel_launch(void* const* d_in, const int* in_sizes, int n_in,
                              void* d_out, int out_size) {
    const float* ml    = (const float*)d_in[0];  // mixture_latent
    const float* trajw = (const float*)d_in[1];  // per_traj_weight
    const float* stepw = (const float*)d_in[2];  // per_step_weight
    float* out = (float*)d_out;

    mdn_fused<<<GRID_TOTAL, 256>>>(ml, trajw, stepw, out);
}